// round 4
// baseline (speedup 1.0000x reference)
#include <cuda_runtime.h>
#include <cuda_bf16.h>
#include <math.h>

#define N_NODES 40000
#define E_EDGES 1280000
#define S_DIM 64
#define V_DIM 16
#define R_DIM 32

// Per-node attention projections (Pa includes ba1), computed by proj_kernel.
__device__ float g_Pa[N_NODES * S_DIM];
__device__ float g_Pb[N_NODES * S_DIM];

// ---------------------------------------------------------------------------
// Kernel 1: initialize output = [scalars ; vectors]
// ---------------------------------------------------------------------------
__global__ void init_out_kernel(const float* __restrict__ scalars,
                                const float* __restrict__ vectors,
                                float* __restrict__ out) {
    const int NS4 = (N_NODES * S_DIM) / 4;          // 640000
    const int NV4 = (N_NODES * V_DIM * 3) / 4;      // 480000
    int i = blockIdx.x * blockDim.x + threadIdx.x;
    if (i < NS4) {
        reinterpret_cast<float4*>(out)[i] =
            reinterpret_cast<const float4*>(scalars)[i];
    } else if (i < NS4 + NV4) {
        reinterpret_cast<float4*>(out)[i] =
            reinterpret_cast<const float4*>(vectors)[i - NS4];
    }
}

// ---------------------------------------------------------------------------
// Kernel 2: per-node projections Pa = ba1 + scalars @ Wa1[0:64],
//                                 Pb =      scalars @ Wa1[64:128]
// ---------------------------------------------------------------------------
#define PROJ_NB 16
__global__ __launch_bounds__(256) void proj_kernel(
    const float* __restrict__ scalars,
    const float* __restrict__ Wa1,
    const float* __restrict__ ba1) {
    __shared__ __align__(16) float sW[128 * 64];
    __shared__ __align__(16) float sS[PROJ_NB * 64];

    const int tid = threadIdx.x;
    const int n0 = blockIdx.x * PROJ_NB;

    for (int i = tid; i < 128 * 64; i += 256) sW[i] = Wa1[i];
    for (int i = tid; i < PROJ_NB * 64; i += 256) sS[i] = scalars[n0 * 64 + i];
    __syncthreads();

    const int j = tid & 63;
    const int grp = tid >> 6;

    const float b = __ldg(&ba1[j]);
    for (int nn = grp; nn < PROJ_NB; nn += 4) {
        float pa = b;
        float pb = 0.0f;
#pragma unroll 8
        for (int k = 0; k < 64; k++) {
            float s = sS[nn * 64 + k];
            pa = fmaf(s, sW[k * 64 + j], pa);
            pb = fmaf(s, sW[(64 + k) * 64 + j], pb);
        }
        g_Pa[(n0 + nn) * 64 + j] = pa;
        g_Pb[(n0 + nn) * 64 + j] = pb;
    }
}

// ---------------------------------------------------------------------------
// Kernel 3: edge kernel.
// Lane j owns output columns (2j, 2j+1) so scatter uses red.global.v2.f32.add
// and gathers use float2 loads.
// ---------------------------------------------------------------------------
__device__ __forceinline__ float silu_f(float x) {
    return x / (1.0f + __expf(-x));
}
__device__ __forceinline__ float dot4(float4 a, float4 b) {
    return fmaf(a.x, b.x, fmaf(a.y, b.y, fmaf(a.z, b.z, a.w * b.w)));
}
__device__ __forceinline__ void red_add_v2(float* ptr, float x, float y) {
    asm volatile("red.global.v2.f32.add [%0], {%1, %2};"
                 :: "l"(ptr), "f"(x), "f"(y) : "memory");
}

__global__ __launch_bounds__(256) void edge_kernel(
    const float* __restrict__ edge_vec,
    const int* __restrict__ ei,          // int32 (JAX default: no x64)
    const float* __restrict__ scalars,
    const float* __restrict__ vectors,
    const float* __restrict__ W1,
    const float* __restrict__ b1,
    const float* __restrict__ W2,
    const float* __restrict__ b2,
    const float* __restrict__ Wa1,
    const float* __restrict__ Wa2,
    const float* __restrict__ ba2,
    float* __restrict__ out) {

    __shared__ __align__(16) float sW1[8 * 32 * 4];     // [g][j][i] = W1[(4g+i)*32 + j]
    // sW2 [g][c][j][i]: c<2 -> W2 col 2j+c ; c==2 -> W2 col 64+j
    __shared__ __align__(16) float sW2[8 * 3 * 32 * 4];
    // sWr [g][c][j][i]: Wa1 rows 128+4g+i, col 2j+c
    __shared__ __align__(16) float sWr[8 * 2 * 32 * 4];
    __shared__ __align__(16) float sB1[32];
    __shared__ __align__(16) float sB2[96];
    __shared__ __align__(16) float sWa2[64];
    __shared__ __align__(16) float sRbf[8][4][32];
    __shared__ __align__(16) float sH1[8][4][32];

    const int tid = threadIdx.x;
    for (int idx = tid; idx < 1024; idx += 256) {
        int g = idx >> 7, r = idx & 127, j = r >> 2, i = r & 3;
        sW1[idx] = W1[(4 * g + i) * 32 + j];
    }
    for (int idx = tid; idx < 3072; idx += 256) {
        int g = idx / 384, r = idx % 384;
        int c = r >> 7, r2 = r & 127, j = r2 >> 2, i = r2 & 3;
        int col = (c < 2) ? (2 * j + c) : (64 + j);
        sW2[idx] = W2[(4 * g + i) * 96 + col];
    }
    for (int idx = tid; idx < 2048; idx += 256) {
        int g = idx >> 8, r = idx & 255;
        int c = r >> 7, r2 = r & 127, j = r2 >> 2, i = r2 & 3;
        sWr[idx] = Wa1[(128 + 4 * g + i) * 64 + 2 * j + c];
    }
    if (tid < 32) sB1[tid] = b1[tid];
    if (tid < 96) sB2[tid] = b2[tid];
    if (tid < 64) sWa2[tid] = Wa2[tid];
    __syncthreads();

    const int warp = tid >> 5;
    const int lane = tid & 31;
    const float ba2v = __ldg(&ba2[0]);
    float* __restrict__ outS = out;
    float* __restrict__ outV = out + N_NODES * S_DIM;

    // precompute vector-part shuffle indices for this lane (pairs 2l, 2l+1)
    const int i0 = 2 * lane;               // 0..62
    const int i1 = 2 * lane + 1;           // 1..63
    const int vi0 = (i0 < 48 ? i0 : 45) / 3, vc0 = (i0 < 48 ? i0 : 45) % 3;
    const int vi1 = (i1 < 48 ? i1 : 46) / 3, vc1 = (i1 < 48 ? i1 : 46) % 3;

    const int NTILES = E_EDGES / 32;   // 40000

    for (int tile = blockIdx.x; tile < NTILES; tile += gridDim.x) {
        const int e0 = tile * 32 + warp * 4;

        __syncwarp();   // protect sRbf/sH1 reuse across tile iterations

        int src[4], dst[4];
        float ux[4], uy[4], uz[4];
#pragma unroll
        for (int t = 0; t < 4; t++) {
            const int e = e0 + t;
            float x = __ldg(&edge_vec[3 * e + 0]);
            float y = __ldg(&edge_vec[3 * e + 1]);
            float z = __ldg(&edge_vec[3 * e + 2]);
            float d = sqrtf(fmaf(x, x, fmaf(y, y, z * z)));
            float ds = fmaxf(d, 1e-8f);
            float iv = 1.0f / ds;
            float ct = (d < 10.0f) ? 0.5f * (cospif(d * 0.1f) + 1.0f) : 0.0f;
            ux[t] = x * iv; uy[t] = y * iv; uz[t] = z * iv;
            float arg = d * 0.1f * (float)(lane + 1);
            sRbf[warp][t][lane] = sinpif(arg) * iv * ct;
            src[t] = __ldg(&ei[e]);
            dst[t] = __ldg(&ei[E_EDGES + e]);
        }
        __syncwarp();

        // ---- h1 = silu(rbf @ W1 + b1) ----  (hidden col = lane, unchanged)
        float acc[4];
        {
            float bb = sB1[lane];
#pragma unroll
            for (int t = 0; t < 4; t++) acc[t] = bb;
        }
#pragma unroll
        for (int g = 0; g < 8; g++) {
            float4 w = *reinterpret_cast<const float4*>(&sW1[g * 128 + lane * 4]);
#pragma unroll
            for (int t = 0; t < 4; t++) {
                float4 r = *reinterpret_cast<const float4*>(&sRbf[warp][t][g * 4]);
                acc[t] += dot4(w, r);
            }
        }
#pragma unroll
        for (int t = 0; t < 4; t++) sH1[warp][t][lane] = silu_f(acc[t]);
        __syncwarp();

        // ---- filters (cols 2l, 2l+1, 64+l) and attention hidden (cols 2l, 2l+1) ----
        float f0[4], f1[4], f2[4], a0[4], a1[4];
        {
            float bb0 = sB2[2 * lane], bb1 = sB2[2 * lane + 1], bb2 = sB2[64 + lane];
#pragma unroll
            for (int t = 0; t < 4; t++) {
                f0[t] = bb0; f1[t] = bb1; f2[t] = bb2;
                float2 pa = *reinterpret_cast<const float2*>(&g_Pa[dst[t] * 64 + 2 * lane]);
                float2 pb = *reinterpret_cast<const float2*>(&g_Pb[src[t] * 64 + 2 * lane]);
                a0[t] = pa.x + pb.x;
                a1[t] = pa.y + pb.y;
            }
        }
#pragma unroll
        for (int g = 0; g < 8; g++) {
            float4 w20 = *reinterpret_cast<const float4*>(&sW2[g * 384 + 0 * 128 + lane * 4]);
            float4 w21 = *reinterpret_cast<const float4*>(&sW2[g * 384 + 1 * 128 + lane * 4]);
            float4 w22 = *reinterpret_cast<const float4*>(&sW2[g * 384 + 2 * 128 + lane * 4]);
            float4 wr0 = *reinterpret_cast<const float4*>(&sWr[g * 256 + 0 * 128 + lane * 4]);
            float4 wr1 = *reinterpret_cast<const float4*>(&sWr[g * 256 + 1 * 128 + lane * 4]);
#pragma unroll
            for (int t = 0; t < 4; t++) {
                float4 h = *reinterpret_cast<const float4*>(&sH1[warp][t][g * 4]);
                float4 r = *reinterpret_cast<const float4*>(&sRbf[warp][t][g * 4]);
                f0[t] += dot4(w20, h);
                f1[t] += dot4(w21, h);
                f2[t] += dot4(w22, h);
                a0[t] += dot4(wr0, r);
                a1[t] += dot4(wr1, r);
            }
        }

        // ---- att = sigmoid(silu(h) @ Wa2 + ba2) ----
        float att[4];
        {
            float wlo = sWa2[2 * lane], whi = sWa2[2 * lane + 1];
#pragma unroll
            for (int t = 0; t < 4; t++) {
                float p = fmaf(silu_f(a0[t]), wlo, silu_f(a1[t]) * whi);
                p += __shfl_xor_sync(0xffffffffu, p, 16);
                p += __shfl_xor_sync(0xffffffffu, p, 8);
                p += __shfl_xor_sync(0xffffffffu, p, 4);
                p += __shfl_xor_sync(0xffffffffu, p, 2);
                p += __shfl_xor_sync(0xffffffffu, p, 1);
                att[t] = 1.0f / (1.0f + __expf(-(p + ba2v)));
            }
        }

        // ---- messages + vector scatter-add ----
#pragma unroll
        for (int t = 0; t < 4; t++) {
            const float a = att[t];
            // scalar message: cols (2l, 2l+1)
            float2 s2 = *reinterpret_cast<const float2*>(&scalars[src[t] * 64 + 2 * lane]);
            red_add_v2(&outS[dst[t] * 64 + 2 * lane], a * s2.x * f0[t], a * s2.y * f1[t]);

            // vector message: elems (2l, 2l+1), lanes 0..23 active
            float vf0 = __shfl_sync(0xffffffffu, f2[t], vi0);
            float vg0 = __shfl_sync(0xffffffffu, f2[t], vi0 + 16);
            float vf1 = __shfl_sync(0xffffffffu, f2[t], vi1);
            float vg1 = __shfl_sync(0xffffffffu, f2[t], vi1 + 16);
            if (lane < 24) {
                float2 vv = *reinterpret_cast<const float2*>(&vectors[src[t] * 48 + i0]);
                float shc0 = (vc0 == 0) ? uy[t] : ((vc0 == 1) ? uz[t] : ux[t]);
                float shc1 = (vc1 == 0) ? uy[t] : ((vc1 == 1) ? uz[t] : ux[t]);
                float m0 = a * fmaf(vv.x, vf0, vg0 * shc0);
                float m1 = a * fmaf(vv.y, vf1, vg1 * shc1);
                red_add_v2(&outV[dst[t] * 48 + i0], m0, m1);
            }
        }
    }
}

// ---------------------------------------------------------------------------
extern "C" void kernel_launch(void* const* d_in, const int* in_sizes, int n_in,
                              void* d_out, int out_size) {
    const float* scalars = (const float*)d_in[0];
    const float* vectors = (const float*)d_in[1];
    const float* edge_vec = (const float*)d_in[2];
    const float* W1 = (const float*)d_in[3];
    const float* b1 = (const float*)d_in[4];
    const float* W2 = (const float*)d_in[5];
    const float* b2 = (const float*)d_in[6];
    const float* Wa1 = (const float*)d_in[7];
    const float* ba1 = (const float*)d_in[8];
    const float* Wa2 = (const float*)d_in[9];
    const float* ba2 = (const float*)d_in[10];
    const int* ei = (const int*)d_in[11];
    float* out = (float*)d_out;

    const int TOT4 = (N_NODES * S_DIM + N_NODES * V_DIM * 3) / 4;  // 1,120,000
    init_out_kernel<<<(TOT4 + 255) / 256, 256>>>(scalars, vectors, out);
    proj_kernel<<<N_NODES / 16, 256>>>(scalars, Wa1, ba1);
    edge_kernel<<<1184, 256>>>(edge_vec, ei, scalars, vectors,
                               W1, b1, W2, b2, Wa1, Wa2, ba2, out);
}

// round 5
// speedup vs baseline: 2.6324x; 2.6324x over previous
#include <cuda_runtime.h>
#include <cuda_bf16.h>
#include <math.h>

#define N_NODES 40000
#define E_EDGES 1280000
#define S_DIM 64
#define V_DIM 16
#define R_DIM 32

#define TBINS 4096
#define TROWS 4098           // rows 0..4096 at d=i*10/4096; row 4097 duplicates 4096
#define TCOLS 160

// Per-node attention projections (Pa includes ba1).
__device__ __align__(16) float g_Pa[N_NODES * S_DIM];
__device__ __align__(16) float g_Pb[N_NODES * S_DIM];
// Distance table: row = [filters[0:64] | proj_r[0:64] | filters[64:96]]
__device__ __align__(16) float g_tab[TROWS * TCOLS];

__device__ __forceinline__ float silu_f(float x) {
    return x / (1.0f + __expf(-x));
}

// ---------------------------------------------------------------------------
// Kernel 1: initialize output = [scalars ; vectors]
// ---------------------------------------------------------------------------
__global__ void init_out_kernel(const float* __restrict__ scalars,
                                const float* __restrict__ vectors,
                                float* __restrict__ out) {
    const int NS4 = (N_NODES * S_DIM) / 4;
    const int NV4 = (N_NODES * V_DIM * 3) / 4;
    int i = blockIdx.x * blockDim.x + threadIdx.x;
    if (i < NS4) {
        reinterpret_cast<float4*>(out)[i] =
            reinterpret_cast<const float4*>(scalars)[i];
    } else if (i < NS4 + NV4) {
        reinterpret_cast<float4*>(out)[i] =
            reinterpret_cast<const float4*>(vectors)[i - NS4];
    }
}

// ---------------------------------------------------------------------------
// Kernel 2: per-node projections Pa = ba1 + scalars @ Wa1[0:64],
//                                 Pb =      scalars @ Wa1[64:128]
// ---------------------------------------------------------------------------
#define PROJ_NB 16
__global__ __launch_bounds__(256) void proj_kernel(
    const float* __restrict__ scalars,
    const float* __restrict__ Wa1,
    const float* __restrict__ ba1) {
    __shared__ __align__(16) float sW[128 * 64];
    __shared__ __align__(16) float sS[PROJ_NB * 64];

    const int tid = threadIdx.x;
    const int n0 = blockIdx.x * PROJ_NB;

    for (int i = tid; i < 128 * 64; i += 256) sW[i] = Wa1[i];
    for (int i = tid; i < PROJ_NB * 64; i += 256) sS[i] = scalars[n0 * 64 + i];
    __syncthreads();

    const int j = tid & 63;
    const int grp = tid >> 6;

    const float b = __ldg(&ba1[j]);
    for (int nn = grp; nn < PROJ_NB; nn += 4) {
        float pa = b;
        float pb = 0.0f;
#pragma unroll 8
        for (int k = 0; k < 64; k++) {
            float s = sS[nn * 64 + k];
            pa = fmaf(s, sW[k * 64 + j], pa);
            pb = fmaf(s, sW[(64 + k) * 64 + j], pb);
        }
        g_Pa[(n0 + nn) * 64 + j] = pa;
        g_Pb[(n0 + nn) * 64 + j] = pb;
    }
}

// ---------------------------------------------------------------------------
// Kernel 2b: distance table. One block (160 threads) per row.
// Row layout: [0:64)  = filters[0:64]   (scalar filter)
//             [64:128)= rbf @ Wa1[128:160]  (attention proj)
//             [128:160)= filters[64:96] (vector filter 16 | gate 16)
// ---------------------------------------------------------------------------
__global__ __launch_bounds__(160) void table_kernel(
    const float* __restrict__ W1, const float* __restrict__ b1,
    const float* __restrict__ W2, const float* __restrict__ b2,
    const float* __restrict__ Wa1) {
    __shared__ float rbf[32];
    __shared__ float h[32];
    const int row = blockIdx.x;
    const int tid = threadIdx.x;
    const float d = fminf((float)row, (float)TBINS) * (10.0f / TBINS);

    if (tid < 32) {
        float freq01 = 0.1f * (float)(tid + 1);          // sinpif arg scale
        float ds = fmaxf(d, 1e-8f);
        float bess;
        if (d < 1e-6f) bess = (float)M_PI * freq01;      // limit sin(wd)/d -> w
        else           bess = sinpif(d * freq01) / ds;
        float cut = (d < 10.0f) ? 0.5f * (cospif(d * 0.1f) + 1.0f) : 0.0f;
        rbf[tid] = bess * cut;
    }
    __syncthreads();
    if (tid < 32) {
        float acc = b1[tid];
#pragma unroll 8
        for (int k = 0; k < 32; k++) acc = fmaf(rbf[k], W1[k * 32 + tid], acc);
        h[tid] = silu_f(acc);
    }
    __syncthreads();

    float out;
    if (tid < 64) {                       // A: filters[tid]
        float acc = b2[tid];
#pragma unroll 8
        for (int j = 0; j < 32; j++) acc = fmaf(h[j], W2[j * 96 + tid], acc);
        out = acc;
    } else if (tid < 128) {               // B: proj[tid-64]
        int c = tid - 64;
        float acc = 0.0f;
#pragma unroll 8
        for (int k = 0; k < 32; k++) acc = fmaf(rbf[k], Wa1[(128 + k) * 64 + c], acc);
        out = acc;
    } else {                              // C: filters[64 + tid-128]
        int c = 64 + tid - 128;
        float acc = b2[c];
#pragma unroll 8
        for (int j = 0; j < 32; j++) acc = fmaf(h[j], W2[j * 96 + c], acc);
        out = acc;
    }
    g_tab[row * TCOLS + tid] = out;
}

// ---------------------------------------------------------------------------
// Kernel 3: edge kernel. 8 warps/block, 4 edges per warp, no shared memory.
// Lane j owns output columns (2j, 2j+1).
// ---------------------------------------------------------------------------
__device__ __forceinline__ void red_add_v2(float* ptr, float x, float y) {
    asm volatile("red.global.v2.f32.add [%0], {%1, %2};"
                 :: "l"(ptr), "f"(x), "f"(y) : "memory");
}

__global__ __launch_bounds__(256) void edge_kernel(
    const float* __restrict__ edge_vec,
    const int* __restrict__ ei,
    const float* __restrict__ scalars,
    const float* __restrict__ vectors,
    const float* __restrict__ Wa2,
    const float* __restrict__ ba2,
    float* __restrict__ out) {

    const int tid = threadIdx.x;
    const int warp = tid >> 5;
    const int lane = tid & 31;
    const float ba2v = __ldg(&ba2[0]);
    const float wlo = __ldg(&Wa2[2 * lane]);
    const float whi = __ldg(&Wa2[2 * lane + 1]);
    float* __restrict__ outS = out;
    float* __restrict__ outV = out + N_NODES * S_DIM;

    // vector-part lane mapping (pairs 2l, 2l+1), lanes 0..23 active
    const int i0 = 2 * lane;
    const int i1 = 2 * lane + 1;
    const int vi0 = (i0 < 48 ? i0 : 45) / 3, vc0 = (i0 < 48 ? i0 : 45) % 3;
    const int vi1 = (i1 < 48 ? i1 : 46) / 3, vc1 = (i1 < 48 ? i1 : 46) % 3;

    const int NTILES = E_EDGES / 32;   // 40000 (32 edges per block-tile)

    for (int tile = blockIdx.x; tile < NTILES; tile += gridDim.x) {
        const int e0 = tile * 32 + warp * 4;

#pragma unroll
        for (int t = 0; t < 4; t++) {
            const int e = e0 + t;
            // ---- geometry ----
            float x = __ldg(&edge_vec[3 * e + 0]);
            float y = __ldg(&edge_vec[3 * e + 1]);
            float z = __ldg(&edge_vec[3 * e + 2]);
            float d = sqrtf(fmaf(x, x, fmaf(y, y, z * z)));
            float iv = 1.0f / fmaxf(d, 1e-8f);
            float ux = x * iv, uy = y * iv, uz = z * iv;
            int src = __ldg(&ei[e]);
            int dst = __ldg(&ei[E_EDGES + e]);

            // ---- table interp ----
            float dn = d * ((float)TBINS / 10.0f);
            int bin = min((int)dn, TBINS);
            float w = dn - (float)bin;            // rows bin, bin+1 (4097 dup of 4096)
            const float* r0 = g_tab + bin * TCOLS;
            const float* r1 = r0 + TCOLS;

            float2 A0 = *reinterpret_cast<const float2*>(r0 + 2 * lane);
            float2 A1 = *reinterpret_cast<const float2*>(r1 + 2 * lane);
            float2 B0 = *reinterpret_cast<const float2*>(r0 + 64 + 2 * lane);
            float2 B1 = *reinterpret_cast<const float2*>(r1 + 64 + 2 * lane);
            float  C0 = __ldg(r0 + 128 + lane);
            float  C1 = __ldg(r1 + 128 + lane);

            float f0 = fmaf(w, A1.x - A0.x, A0.x);
            float f1 = fmaf(w, A1.y - A0.y, A0.y);
            float f2 = fmaf(w, C1 - C0, C0);
            float p0 = fmaf(w, B1.x - B0.x, B0.x);
            float p1 = fmaf(w, B1.y - B0.y, B0.y);

            // ---- attention ----
            float2 pa = *reinterpret_cast<const float2*>(&g_Pa[dst * 64 + 2 * lane]);
            float2 pb = *reinterpret_cast<const float2*>(&g_Pb[src * 64 + 2 * lane]);
            float a0 = pa.x + pb.x + p0;
            float a1 = pa.y + pb.y + p1;
            float p = fmaf(silu_f(a0), wlo, silu_f(a1) * whi);
            p += __shfl_xor_sync(0xffffffffu, p, 16);
            p += __shfl_xor_sync(0xffffffffu, p, 8);
            p += __shfl_xor_sync(0xffffffffu, p, 4);
            p += __shfl_xor_sync(0xffffffffu, p, 2);
            p += __shfl_xor_sync(0xffffffffu, p, 1);
            float att = 1.0f / (1.0f + __expf(-(p + ba2v)));

            // ---- scalar message ----
            float2 s2 = *reinterpret_cast<const float2*>(&scalars[src * 64 + 2 * lane]);
            red_add_v2(&outS[dst * 64 + 2 * lane], att * s2.x * f0, att * s2.y * f1);

            // ---- vector message ----
            float vf0 = __shfl_sync(0xffffffffu, f2, vi0);
            float vg0 = __shfl_sync(0xffffffffu, f2, vi0 + 16);
            float vf1 = __shfl_sync(0xffffffffu, f2, vi1);
            float vg1 = __shfl_sync(0xffffffffu, f2, vi1 + 16);
            if (lane < 24) {
                float2 vv = *reinterpret_cast<const float2*>(&vectors[src * 48 + i0]);
                float shc0 = (vc0 == 0) ? uy : ((vc0 == 1) ? uz : ux);
                float shc1 = (vc1 == 0) ? uy : ((vc1 == 1) ? uz : ux);
                float m0 = att * fmaf(vv.x, vf0, vg0 * shc0);
                float m1 = att * fmaf(vv.y, vf1, vg1 * shc1);
                red_add_v2(&outV[dst * 48 + i0], m0, m1);
            }
        }
    }
}

// ---------------------------------------------------------------------------
extern "C" void kernel_launch(void* const* d_in, const int* in_sizes, int n_in,
                              void* d_out, int out_size) {
    const float* scalars = (const float*)d_in[0];
    const float* vectors = (const float*)d_in[1];
    const float* edge_vec = (const float*)d_in[2];
    const float* W1 = (const float*)d_in[3];
    const float* b1 = (const float*)d_in[4];
    const float* W2 = (const float*)d_in[5];
    const float* b2 = (const float*)d_in[6];
    const float* Wa1 = (const float*)d_in[7];
    const float* ba1 = (const float*)d_in[8];
    const float* Wa2 = (const float*)d_in[9];
    const float* ba2 = (const float*)d_in[10];
    const int* ei = (const int*)d_in[11];
    float* out = (float*)d_out;

    const int TOT4 = (N_NODES * S_DIM + N_NODES * V_DIM * 3) / 4;
    init_out_kernel<<<(TOT4 + 255) / 256, 256>>>(scalars, vectors, out);
    table_kernel<<<TROWS, 160>>>(W1, b1, W2, b2, Wa1);
    proj_kernel<<<N_NODES / 16, 256>>>(scalars, Wa1, ba1);
    edge_kernel<<<4000, 256>>>(edge_vec, ei, scalars, vectors, Wa2, ba2, out);
}

// round 6
// speedup vs baseline: 3.0547x; 1.1604x over previous
#include <cuda_runtime.h>
#include <cuda_bf16.h>
#include <math.h>

#define N_NODES 40000
#define E_EDGES 1280000
#define S_DIM 64
#define V_DIM 16
#define R_DIM 32

#define TBINS 4096
#define RAW_ROWS 4098        // raw rows 0..4097 (4097 duplicates 4096)
#define RAW_COLS 160
#define PK_ROWS 4097         // packed rows 0..4096 (bin index)
#define PK_COLS 320          // (val,slope) packed, 1280 bytes/row

// Per-node data
__device__ __align__(16) float g_Pa[N_NODES * S_DIM];          // dst attention proj (incl ba1)
__device__ __align__(16) float g_SrcRow[N_NODES * 128];        // [Pb|scalars] interleaved per pair
// Distance tables
__device__ __align__(16) float g_raw[RAW_ROWS * RAW_COLS];     // raw values
__device__ __align__(16) float g_tab[PK_ROWS * PK_COLS];       // packed val/slope

__device__ __forceinline__ float silu_f(float x) {
    return x / (1.0f + __expf(-x));
}
__device__ __forceinline__ void red_add_v2(float* ptr, float x, float y) {
    asm volatile("red.global.v2.f32.add [%0], {%1, %2};"
                 :: "l"(ptr), "f"(x), "f"(y) : "memory");
}

// ---------------------------------------------------------------------------
// Kernel 1: initialize output = [scalars ; vectors]
// ---------------------------------------------------------------------------
__global__ void init_out_kernel(const float* __restrict__ scalars,
                                const float* __restrict__ vectors,
                                float* __restrict__ out) {
    const int NS4 = (N_NODES * S_DIM) / 4;
    const int NV4 = (N_NODES * V_DIM * 3) / 4;
    int i = blockIdx.x * blockDim.x + threadIdx.x;
    if (i < NS4) {
        reinterpret_cast<float4*>(out)[i] =
            reinterpret_cast<const float4*>(scalars)[i];
    } else if (i < NS4 + NV4) {
        reinterpret_cast<float4*>(out)[i] =
            reinterpret_cast<const float4*>(vectors)[i - NS4];
    }
}

// ---------------------------------------------------------------------------
// Kernel 2: per-node projections. Pa = ba1 + s@Wa1[0:64] -> g_Pa
//           Pb = s@Wa1[64:128] and scalars -> fused g_SrcRow
// ---------------------------------------------------------------------------
#define PROJ_NB 16
__global__ __launch_bounds__(256) void proj_kernel(
    const float* __restrict__ scalars,
    const float* __restrict__ Wa1,
    const float* __restrict__ ba1) {
    __shared__ __align__(16) float sW[128 * 64];
    __shared__ __align__(16) float sS[PROJ_NB * 64];

    const int tid = threadIdx.x;
    const int n0 = blockIdx.x * PROJ_NB;

    for (int i = tid; i < 128 * 64; i += 256) sW[i] = Wa1[i];
    for (int i = tid; i < PROJ_NB * 64; i += 256) sS[i] = scalars[n0 * 64 + i];
    __syncthreads();

    const int j = tid & 63;
    const int grp = tid >> 6;

    const float b = __ldg(&ba1[j]);
    for (int nn = grp; nn < PROJ_NB; nn += 4) {
        float pa = b;
        float pb = 0.0f;
#pragma unroll 8
        for (int k = 0; k < 64; k++) {
            float s = sS[nn * 64 + k];
            pa = fmaf(s, sW[k * 64 + j], pa);
            pb = fmaf(s, sW[(64 + k) * 64 + j], pb);
        }
        const int node = n0 + nn;
        g_Pa[node * 64 + j] = pa;
        int base = node * 128 + (j >> 1) * 4 + (j & 1);
        g_SrcRow[base] = pb;
        g_SrcRow[base + 2] = sS[nn * 64 + j];
    }
}

// ---------------------------------------------------------------------------
// Kernel 2b: raw distance table. One block (160 threads) per row.
// Raw row: [0:64) filters[0:64] | [64:128) rbf@Wa1[128:160] | [128:160) filters[64:96]
// ---------------------------------------------------------------------------
__global__ __launch_bounds__(160) void table_kernel(
    const float* __restrict__ W1, const float* __restrict__ b1,
    const float* __restrict__ W2, const float* __restrict__ b2,
    const float* __restrict__ Wa1) {
    __shared__ float rbf[32];
    __shared__ float h[32];
    const int row = blockIdx.x;
    const int tid = threadIdx.x;
    const float d = fminf((float)row, (float)TBINS) * (10.0f / TBINS);

    if (tid < 32) {
        float freq01 = 0.1f * (float)(tid + 1);
        float ds = fmaxf(d, 1e-8f);
        float bess;
        if (d < 1e-6f) bess = (float)M_PI * freq01;
        else           bess = sinpif(d * freq01) / ds;
        float cut = (d < 10.0f) ? 0.5f * (cospif(d * 0.1f) + 1.0f) : 0.0f;
        rbf[tid] = bess * cut;
    }
    __syncthreads();
    if (tid < 32) {
        float acc = b1[tid];
#pragma unroll 8
        for (int k = 0; k < 32; k++) acc = fmaf(rbf[k], W1[k * 32 + tid], acc);
        h[tid] = silu_f(acc);
    }
    __syncthreads();

    float outv;
    if (tid < 64) {
        float acc = b2[tid];
#pragma unroll 8
        for (int jj = 0; jj < 32; jj++) acc = fmaf(h[jj], W2[jj * 96 + tid], acc);
        outv = acc;
    } else if (tid < 128) {
        int c = tid - 64;
        float acc = 0.0f;
#pragma unroll 8
        for (int k = 0; k < 32; k++) acc = fmaf(rbf[k], Wa1[(128 + k) * 64 + c], acc);
        outv = acc;
    } else {
        int c = 64 + tid - 128;
        float acc = b2[c];
#pragma unroll 8
        for (int jj = 0; jj < 32; jj++) acc = fmaf(h[jj], W2[jj * 96 + c], acc);
        outv = acc;
    }
    g_raw[row * RAW_COLS + tid] = outv;
}

// ---------------------------------------------------------------------------
// Kernel 2c: pack raw -> (val, slope) rows.
// Packed row (320 floats):
//  [0:128)   A: j=0..31: (fv[2j], fv[2j+1], fslope[2j], fslope[2j+1])
//  [128:256) B: same for attention proj (raw cols 64..127)
//  [256:320) C: j=0..31: (Cv[j], Cslope[j])  (raw cols 128..159)
// ---------------------------------------------------------------------------
__global__ __launch_bounds__(320) void pack_kernel() {
    const int row = blockIdx.x;           // 0..4096
    const int t = threadIdx.x;            // 0..319
    const float* r0 = g_raw + row * RAW_COLS;
    const float* r1 = r0 + RAW_COLS;
    float v;
    if (t < 128) {
        int j = t >> 2, k = t & 3;
        int col = 2 * j + (k & 1);
        v = (k < 2) ? r0[col] : (r1[col] - r0[col]);
    } else if (t < 256) {
        int u = t - 128;
        int j = u >> 2, k = u & 3;
        int col = 64 + 2 * j + (k & 1);
        v = (k < 2) ? r0[col] : (r1[col] - r0[col]);
    } else {
        int u = t - 256;
        int j = u >> 1, k = u & 1;
        int col = 128 + j;
        v = (k == 0) ? r0[col] : (r1[col] - r0[col]);
    }
    g_tab[row * PK_COLS + t] = v;
}

// ---------------------------------------------------------------------------
// Kernel 3: edge kernel. Each warp owns a 32-edge tile.
// Phase A: lane-parallel geometry + offset precompute (per-lane, one edge each).
// Phase B: loop t=0..31, broadcast via shfl, per-edge math, scatter.
// ---------------------------------------------------------------------------
__global__ __launch_bounds__(256) void edge_kernel(
    const float* __restrict__ edge_vec,
    const int* __restrict__ ei,
    const float* __restrict__ vectors,
    const float* __restrict__ Wa2,
    const float* __restrict__ ba2,
    float* __restrict__ out) {

    const int tid = threadIdx.x;
    const int warp = tid >> 5;
    const int lane = tid & 31;
    const float ba2v = __ldg(&ba2[0]);
    const float wlo = __ldg(&Wa2[2 * lane]);
    const float whi = __ldg(&Wa2[2 * lane + 1]);

    const char* tabBase = (const char*)g_tab;
    const char* paBase = (const char*)g_Pa;
    const char* srBase = (const char*)g_SrcRow;
    const char* vecBase = (const char*)vectors;
    char* outSBase = (char*)out;
    char* outVBase = (char*)(out + N_NODES * S_DIM);

    // per-lane byte offsets within rows
    const unsigned laneA = lane * 16u;
    const unsigned laneB = 512u + lane * 16u;
    const unsigned laneC = 1024u + lane * 8u;
    const unsigned lane8 = lane * 8u;       // Pa / outS
    const unsigned lane16 = lane * 16u;     // SrcRow
    // vector-part lane mapping (pairs 2l, 2l+1), lanes 0..23 active
    const int i0 = 2 * lane;
    const int i1 = 2 * lane + 1;
    const int vi0 = (i0 < 48 ? i0 : 45) / 3, vc0 = (i0 < 48 ? i0 : 45) % 3;
    const int vi1 = (i1 < 48 ? i1 : 46) / 3, vc1 = (i1 < 48 ? i1 : 46) % 3;
    const unsigned laneV = (unsigned)i0 * 4u;

    const int NWT = E_EDGES / 32;   // 40000 warp-tiles

    for (int wt = blockIdx.x * 8 + warp; wt < NWT; wt += gridDim.x * 8) {
        const int e = wt * 32 + lane;

        // ---- Phase A: lane-parallel geometry for this lane's edge ----
        float x = __ldg(&edge_vec[3 * e + 0]);
        float y = __ldg(&edge_vec[3 * e + 1]);
        float z = __ldg(&edge_vec[3 * e + 2]);
        int sL = __ldg(&ei[e]);
        int dL = __ldg(&ei[E_EDGES + e]);
        float d = sqrtf(fmaf(x, x, fmaf(y, y, z * z)));
        float iv = 1.0f / fmaxf(d, 1e-8f);
        float uxL = x * iv, uyL = y * iv, uzL = z * iv;
        float dn = d * ((float)TBINS / 10.0f);
        int bin = min((int)dn, TBINS);
        float wL = dn - (float)bin;
        unsigned rowOffL = (unsigned)bin * 1280u;
        unsigned dstOffL = (unsigned)dL * 256u;     // g_Pa / outS row
        unsigned srcOffL = (unsigned)sL * 512u;     // g_SrcRow row
        unsigned vsOffL = (unsigned)sL * 192u;      // vectors row
        unsigned vdOffL = (unsigned)dL * 192u;      // outV row

        // ---- Phase B: per-edge processing ----
#pragma unroll 4
        for (int t = 0; t < 32; t++) {
            float w = __shfl_sync(0xffffffffu, wL, t);
            float ux = __shfl_sync(0xffffffffu, uxL, t);
            float uy = __shfl_sync(0xffffffffu, uyL, t);
            float uz = __shfl_sync(0xffffffffu, uzL, t);
            unsigned rowOff = __shfl_sync(0xffffffffu, rowOffL, t);
            unsigned dstOff = __shfl_sync(0xffffffffu, dstOffL, t);
            unsigned srcOff = __shfl_sync(0xffffffffu, srcOffL, t);
            unsigned vsOff = __shfl_sync(0xffffffffu, vsOffL, t);
            unsigned vdOff = __shfl_sync(0xffffffffu, vdOffL, t);

            float4 A = *reinterpret_cast<const float4*>(tabBase + rowOff + laneA);
            float4 B = *reinterpret_cast<const float4*>(tabBase + rowOff + laneB);
            float2 C = *reinterpret_cast<const float2*>(tabBase + rowOff + laneC);
            float2 Pa = *reinterpret_cast<const float2*>(paBase + dstOff + lane8);
            float4 SR = *reinterpret_cast<const float4*>(srBase + srcOff + lane16);

            float f0 = fmaf(w, A.z, A.x);
            float f1 = fmaf(w, A.w, A.y);
            float p0 = fmaf(w, B.z, B.x);
            float p1 = fmaf(w, B.w, B.y);
            float f2 = fmaf(w, C.y, C.x);

            // attention
            float a0 = Pa.x + SR.x + p0;
            float a1 = Pa.y + SR.y + p1;
            float p = fmaf(silu_f(a0), wlo, silu_f(a1) * whi);
            p += __shfl_xor_sync(0xffffffffu, p, 16);
            p += __shfl_xor_sync(0xffffffffu, p, 8);
            p += __shfl_xor_sync(0xffffffffu, p, 4);
            p += __shfl_xor_sync(0xffffffffu, p, 2);
            p += __shfl_xor_sync(0xffffffffu, p, 1);
            float att = 1.0f / (1.0f + __expf(-(p + ba2v)));

            // scalar message
            red_add_v2(reinterpret_cast<float*>(outSBase + dstOff + lane8),
                       att * SR.z * f0, att * SR.w * f1);

            // vector message
            float vf0 = __shfl_sync(0xffffffffu, f2, vi0);
            float vg0 = __shfl_sync(0xffffffffu, f2, vi0 + 16);
            float vf1 = __shfl_sync(0xffffffffu, f2, vi1);
            float vg1 = __shfl_sync(0xffffffffu, f2, vi1 + 16);
            if (lane < 24) {
                float2 vv = *reinterpret_cast<const float2*>(vecBase + vsOff + laneV);
                float shc0 = (vc0 == 0) ? uy : ((vc0 == 1) ? uz : ux);
                float shc1 = (vc1 == 0) ? uy : ((vc1 == 1) ? uz : ux);
                float m0 = att * fmaf(vv.x, vf0, vg0 * shc0);
                float m1 = att * fmaf(vv.y, vf1, vg1 * shc1);
                red_add_v2(reinterpret_cast<float*>(outVBase + vdOff + laneV), m0, m1);
            }
        }
    }
}

// ---------------------------------------------------------------------------
extern "C" void kernel_launch(void* const* d_in, const int* in_sizes, int n_in,
                              void* d_out, int out_size) {
    const float* scalars = (const float*)d_in[0];
    const float* vectors = (const float*)d_in[1];
    const float* edge_vec = (const float*)d_in[2];
    const float* W1 = (const float*)d_in[3];
    const float* b1 = (const float*)d_in[4];
    const float* W2 = (const float*)d_in[5];
    const float* b2 = (const float*)d_in[6];
    const float* Wa1 = (const float*)d_in[7];
    const float* ba1 = (const float*)d_in[8];
    const float* Wa2 = (const float*)d_in[9];
    const float* ba2 = (const float*)d_in[10];
    const int* ei = (const int*)d_in[11];
    float* out = (float*)d_out;

    const int TOT4 = (N_NODES * S_DIM + N_NODES * V_DIM * 3) / 4;
    init_out_kernel<<<(TOT4 + 255) / 256, 256>>>(scalars, vectors, out);
    table_kernel<<<RAW_ROWS, 160>>>(W1, b1, W2, b2, Wa1);
    pack_kernel<<<PK_ROWS, 320>>>();
    proj_kernel<<<N_NODES / PROJ_NB, 256>>>(scalars, Wa1, ba1);
    edge_kernel<<<2500, 256>>>(edge_vec, ei, vectors, Wa2, ba2, out);
}

// round 7
// speedup vs baseline: 3.3276x; 1.0894x over previous
#include <cuda_runtime.h>
#include <cuda_bf16.h>
#include <math.h>

#define N_NODES 40000
#define E_EDGES 1280000
#define S_DIM 64
#define V_DIM 16
#define R_DIM 32

#define TBINS 4096
#define RAW_ROWS 4098        // raw rows 0..4097 (4097 duplicates 4096)
#define RAW_COLS 160
#define PK_ROWS 4097         // packed rows 0..4096 (bin index)
#define PK_COLS 320          // (val,slope) packed, 1280 bytes/row

// Per-node data
__device__ __align__(16) float g_Pa[N_NODES * S_DIM];          // dst attention proj (incl ba1)
__device__ __align__(16) float g_SrcRow[N_NODES * 128];        // [Pb|scalars] interleaved per pair
// Distance tables
__device__ __align__(16) float g_raw[RAW_ROWS * RAW_COLS];     // raw values
__device__ __align__(16) float g_tab[PK_ROWS * PK_COLS];       // packed val/slope

__device__ __forceinline__ float silu_f(float x) {
    return x / (1.0f + __expf(-x));
}
__device__ __forceinline__ void red_add_v2(float* ptr, float x, float y) {
    asm volatile("red.global.v2.f32.add [%0], {%1, %2};"
                 :: "l"(ptr), "f"(x), "f"(y) : "memory");
}

// ---------------------------------------------------------------------------
// Kernel 1: initialize output = [scalars ; vectors]
// ---------------------------------------------------------------------------
__global__ void init_out_kernel(const float* __restrict__ scalars,
                                const float* __restrict__ vectors,
                                float* __restrict__ out) {
    const int NS4 = (N_NODES * S_DIM) / 4;
    const int NV4 = (N_NODES * V_DIM * 3) / 4;
    int i = blockIdx.x * blockDim.x + threadIdx.x;
    if (i < NS4) {
        reinterpret_cast<float4*>(out)[i] =
            reinterpret_cast<const float4*>(scalars)[i];
    } else if (i < NS4 + NV4) {
        reinterpret_cast<float4*>(out)[i] =
            reinterpret_cast<const float4*>(vectors)[i - NS4];
    }
}

// ---------------------------------------------------------------------------
// Kernel 2: per-node projections. Pa = ba1 + s@Wa1[0:64] -> g_Pa
//           Pb = s@Wa1[64:128] and scalars -> fused g_SrcRow
// Register-blocked: 32 nodes/block, 8 nodes per thread, one LDS.64 weight
// pair per k amortized over 8 nodes.
// ---------------------------------------------------------------------------
#define PROJ_NB 32
__global__ __launch_bounds__(256) void proj_kernel(
    const float* __restrict__ scalars,
    const float* __restrict__ Wa1,
    const float* __restrict__ ba1) {
    // interleaved: sWi[k*128 + 2j] = Wa1[k*64+j] (pa), sWi[k*128+2j+1] = Wa1[(64+k)*64+j] (pb)
    __shared__ __align__(16) float sWi[64 * 128];          // 32 KB
    __shared__ __align__(16) float sS[PROJ_NB * 64];       // 8 KB

    const int tid = threadIdx.x;
    const int n0 = blockIdx.x * PROJ_NB;

    for (int idx = tid; idx < 64 * 128; idx += 256) {
        int k = idx >> 7, r = idx & 127, j = r >> 1, h = r & 1;
        sWi[idx] = Wa1[(h * 64 + k) * 64 + j];
    }
    for (int i = tid; i < PROJ_NB * 64; i += 256) sS[i] = scalars[n0 * 64 + i];
    __syncthreads();

    const int j = tid & 63;
    const int grp = tid >> 6;                 // 0..3 -> nodes grp*8 .. grp*8+7
    const float* sbase = &sS[grp * 8 * 64];

    float pa[8], pb[8];
    {
        const float b = __ldg(&ba1[j]);
#pragma unroll
        for (int nn = 0; nn < 8; nn++) { pa[nn] = b; pb[nn] = 0.0f; }
    }

#pragma unroll 4
    for (int k = 0; k < 64; k++) {
        float2 w = *reinterpret_cast<const float2*>(&sWi[k * 128 + 2 * j]);
#pragma unroll
        for (int nn = 0; nn < 8; nn++) {
            float s = sbase[nn * 64 + k];
            pa[nn] = fmaf(s, w.x, pa[nn]);
            pb[nn] = fmaf(s, w.y, pb[nn]);
        }
    }

#pragma unroll
    for (int nn = 0; nn < 8; nn++) {
        const int node = n0 + grp * 8 + nn;
        g_Pa[node * 64 + j] = pa[nn];
        int base = node * 128 + (j >> 1) * 4 + (j & 1);
        g_SrcRow[base] = pb[nn];
        g_SrcRow[base + 2] = sbase[nn * 64 + j];
    }
}

// ---------------------------------------------------------------------------
// Kernel 2b: raw distance table. One block (160 threads) per row.
// Raw row: [0:64) filters[0:64] | [64:128) rbf@Wa1[128:160] | [128:160) filters[64:96]
// ---------------------------------------------------------------------------
__global__ __launch_bounds__(160) void table_kernel(
    const float* __restrict__ W1, const float* __restrict__ b1,
    const float* __restrict__ W2, const float* __restrict__ b2,
    const float* __restrict__ Wa1) {
    __shared__ float rbf[32];
    __shared__ float h[32];
    const int row = blockIdx.x;
    const int tid = threadIdx.x;
    const float d = fminf((float)row, (float)TBINS) * (10.0f / TBINS);

    if (tid < 32) {
        float freq01 = 0.1f * (float)(tid + 1);
        float ds = fmaxf(d, 1e-8f);
        float bess;
        if (d < 1e-6f) bess = (float)M_PI * freq01;
        else           bess = sinpif(d * freq01) / ds;
        float cut = (d < 10.0f) ? 0.5f * (cospif(d * 0.1f) + 1.0f) : 0.0f;
        rbf[tid] = bess * cut;
    }
    __syncthreads();
    if (tid < 32) {
        float acc = b1[tid];
#pragma unroll 8
        for (int k = 0; k < 32; k++) acc = fmaf(rbf[k], W1[k * 32 + tid], acc);
        h[tid] = silu_f(acc);
    }
    __syncthreads();

    float outv;
    if (tid < 64) {
        float acc = b2[tid];
#pragma unroll 8
        for (int jj = 0; jj < 32; jj++) acc = fmaf(h[jj], W2[jj * 96 + tid], acc);
        outv = acc;
    } else if (tid < 128) {
        int c = tid - 64;
        float acc = 0.0f;
#pragma unroll 8
        for (int k = 0; k < 32; k++) acc = fmaf(rbf[k], Wa1[(128 + k) * 64 + c], acc);
        outv = acc;
    } else {
        int c = 64 + tid - 128;
        float acc = b2[c];
#pragma unroll 8
        for (int jj = 0; jj < 32; jj++) acc = fmaf(h[jj], W2[jj * 96 + c], acc);
        outv = acc;
    }
    g_raw[row * RAW_COLS + tid] = outv;
}

// ---------------------------------------------------------------------------
// Kernel 2c: pack raw -> (val, slope) rows.
// Packed row (320 floats):
//  [0:128)   A: j=0..31: (fv[2j], fv[2j+1], fslope[2j], fslope[2j+1])
//  [128:256) B: same for attention proj (raw cols 64..127)
//  [256:320) C: j=0..31: (Cv[j], Cslope[j])  (raw cols 128..159)
// ---------------------------------------------------------------------------
__global__ __launch_bounds__(320) void pack_kernel() {
    const int row = blockIdx.x;           // 0..4096
    const int t = threadIdx.x;            // 0..319
    const float* r0 = g_raw + row * RAW_COLS;
    const float* r1 = r0 + RAW_COLS;
    float v;
    if (t < 128) {
        int j = t >> 2, k = t & 3;
        int col = 2 * j + (k & 1);
        v = (k < 2) ? r0[col] : (r1[col] - r0[col]);
    } else if (t < 256) {
        int u = t - 128;
        int j = u >> 2, k = u & 3;
        int col = 64 + 2 * j + (k & 1);
        v = (k < 2) ? r0[col] : (r1[col] - r0[col]);
    } else {
        int u = t - 256;
        int j = u >> 1, k = u & 1;
        int col = 128 + j;
        v = (k == 0) ? r0[col] : (r1[col] - r0[col]);
    }
    g_tab[row * PK_COLS + t] = v;
}

// ---------------------------------------------------------------------------
// Kernel 3: edge kernel. Each warp owns a 32-edge tile.
// Phase A: lane-parallel geometry + offset precompute.
// Phase B: per-edge broadcast + math + scatter.
// ---------------------------------------------------------------------------
__global__ __launch_bounds__(256) void edge_kernel(
    const float* __restrict__ edge_vec,
    const int* __restrict__ ei,
    const float* __restrict__ vectors,
    const float* __restrict__ Wa2,
    const float* __restrict__ ba2,
    float* __restrict__ out) {

    const int tid = threadIdx.x;
    const int warp = tid >> 5;
    const int lane = tid & 31;
    const float ba2v = __ldg(&ba2[0]);
    const float wlo = __ldg(&Wa2[2 * lane]);
    const float whi = __ldg(&Wa2[2 * lane + 1]);

    const char* tabBase = (const char*)g_tab;
    const char* paBase = (const char*)g_Pa;
    const char* srBase = (const char*)g_SrcRow;
    const char* vecBase = (const char*)vectors;
    char* outSBase = (char*)out;
    char* outVBase = (char*)(out + N_NODES * S_DIM);

    const unsigned laneA = lane * 16u;
    const unsigned laneB = 512u + lane * 16u;
    const unsigned laneC = 1024u + lane * 8u;
    const unsigned lane8 = lane * 8u;
    const unsigned lane16 = lane * 16u;
    const int i0 = 2 * lane;
    const int i1 = 2 * lane + 1;
    const int vi0 = (i0 < 48 ? i0 : 45) / 3, vc0 = (i0 < 48 ? i0 : 45) % 3;
    const int vi1 = (i1 < 48 ? i1 : 46) / 3, vc1 = (i1 < 48 ? i1 : 46) % 3;
    const unsigned laneV = (unsigned)i0 * 4u;

    const int NWT = E_EDGES / 32;

    for (int wt = blockIdx.x * 8 + warp; wt < NWT; wt += gridDim.x * 8) {
        const int e = wt * 32 + lane;

        float x = __ldg(&edge_vec[3 * e + 0]);
        float y = __ldg(&edge_vec[3 * e + 1]);
        float z = __ldg(&edge_vec[3 * e + 2]);
        int sL = __ldg(&ei[e]);
        int dL = __ldg(&ei[E_EDGES + e]);
        float d = sqrtf(fmaf(x, x, fmaf(y, y, z * z)));
        float iv = 1.0f / fmaxf(d, 1e-8f);
        float uxL = x * iv, uyL = y * iv, uzL = z * iv;
        float dn = d * ((float)TBINS / 10.0f);
        int bin = min((int)dn, TBINS);
        float wL = dn - (float)bin;
        unsigned rowOffL = (unsigned)bin * 1280u;
        unsigned dstOffL = (unsigned)dL * 256u;
        unsigned srcOffL = (unsigned)sL * 512u;
        unsigned vsOffL = (unsigned)sL * 192u;
        unsigned vdOffL = (unsigned)dL * 192u;

#pragma unroll 4
        for (int t = 0; t < 32; t++) {
            float w = __shfl_sync(0xffffffffu, wL, t);
            float ux = __shfl_sync(0xffffffffu, uxL, t);
            float uy = __shfl_sync(0xffffffffu, uyL, t);
            float uz = __shfl_sync(0xffffffffu, uzL, t);
            unsigned rowOff = __shfl_sync(0xffffffffu, rowOffL, t);
            unsigned dstOff = __shfl_sync(0xffffffffu, dstOffL, t);
            unsigned srcOff = __shfl_sync(0xffffffffu, srcOffL, t);
            unsigned vsOff = __shfl_sync(0xffffffffu, vsOffL, t);
            unsigned vdOff = __shfl_sync(0xffffffffu, vdOffL, t);

            float4 A = *reinterpret_cast<const float4*>(tabBase + rowOff + laneA);
            float4 B = *reinterpret_cast<const float4*>(tabBase + rowOff + laneB);
            float2 C = *reinterpret_cast<const float2*>(tabBase + rowOff + laneC);
            float2 Pa = *reinterpret_cast<const float2*>(paBase + dstOff + lane8);
            float4 SR = *reinterpret_cast<const float4*>(srBase + srcOff + lane16);

            float f0 = fmaf(w, A.z, A.x);
            float f1 = fmaf(w, A.w, A.y);
            float p0 = fmaf(w, B.z, B.x);
            float p1 = fmaf(w, B.w, B.y);
            float f2 = fmaf(w, C.y, C.x);

            float a0 = Pa.x + SR.x + p0;
            float a1 = Pa.y + SR.y + p1;
            float p = fmaf(silu_f(a0), wlo, silu_f(a1) * whi);
            p += __shfl_xor_sync(0xffffffffu, p, 16);
            p += __shfl_xor_sync(0xffffffffu, p, 8);
            p += __shfl_xor_sync(0xffffffffu, p, 4);
            p += __shfl_xor_sync(0xffffffffu, p, 2);
            p += __shfl_xor_sync(0xffffffffu, p, 1);
            float att = 1.0f / (1.0f + __expf(-(p + ba2v)));

            red_add_v2(reinterpret_cast<float*>(outSBase + dstOff + lane8),
                       att * SR.z * f0, att * SR.w * f1);

            float vf0 = __shfl_sync(0xffffffffu, f2, vi0);
            float vg0 = __shfl_sync(0xffffffffu, f2, vi0 + 16);
            float vf1 = __shfl_sync(0xffffffffu, f2, vi1);
            float vg1 = __shfl_sync(0xffffffffu, f2, vi1 + 16);
            if (lane < 24) {
                float2 vv = *reinterpret_cast<const float2*>(vecBase + vsOff + laneV);
                float shc0 = (vc0 == 0) ? uy : ((vc0 == 1) ? uz : ux);
                float shc1 = (vc1 == 0) ? uy : ((vc1 == 1) ? uz : ux);
                float m0 = att * fmaf(vv.x, vf0, vg0 * shc0);
                float m1 = att * fmaf(vv.y, vf1, vg1 * shc1);
                red_add_v2(reinterpret_cast<float*>(outVBase + vdOff + laneV), m0, m1);
            }
        }
    }
}

// ---------------------------------------------------------------------------
extern "C" void kernel_launch(void* const* d_in, const int* in_sizes, int n_in,
                              void* d_out, int out_size) {
    const float* scalars = (const float*)d_in[0];
    const float* vectors = (const float*)d_in[1];
    const float* edge_vec = (const float*)d_in[2];
    const float* W1 = (const float*)d_in[3];
    const float* b1 = (const float*)d_in[4];
    const float* W2 = (const float*)d_in[5];
    const float* b2 = (const float*)d_in[6];
    const float* Wa1 = (const float*)d_in[7];
    const float* ba1 = (const float*)d_in[8];
    const float* Wa2 = (const float*)d_in[9];
    const float* ba2 = (const float*)d_in[10];
    const int* ei = (const int*)d_in[11];
    float* out = (float*)d_out;

    const int TOT4 = (N_NODES * S_DIM + N_NODES * V_DIM * 3) / 4;
    init_out_kernel<<<(TOT4 + 255) / 256, 256>>>(scalars, vectors, out);
    table_kernel<<<RAW_ROWS, 160>>>(W1, b1, W2, b2, Wa1);
    pack_kernel<<<PK_ROWS, 320>>>();
    proj_kernel<<<N_NODES / PROJ_NB, 256>>>(scalars, Wa1, ba1);
    edge_kernel<<<2500, 256>>>(edge_vec, ei, vectors, Wa2, ba2, out);
}